// round 16
// baseline (speedup 1.0000x reference)
#include <cuda_runtime.h>
#include <cuda_pipeline.h>

#define S  512
#define S2 (S*S)
#define NBATCH 32
#define NBLK_TOTAL 4096u

// Global accumulators (zero at load; finalize resets them each run)
__device__ double g_acc[2] = {0.0, 0.0};         // [0]=sum|cont|, [1]=sum|pois|
__device__ double g_bc4[NBATCH * 4] = {0.0};     // per-batch per-edge signed sums
__device__ unsigned int g_count = 0u;

// Per-thread strip: 2 columns (jA, jB) x 4 rows.
// Row window: gy in [i0-1, i0+32] -> R = gy - i0 + 1 (34 rows).
// u cols: gx = bx*64-4 + c (72 cols); v/p/q cols: gx = bx*64 + c (68 cols).
// jA = j0+2*tx: u col of jA = 2tx+4; v col of jA = 2tx+1. All pair loads even-aligned.
template<bool INT>
__device__ __forceinline__ void tile_compute(
    const float (*__restrict__ su)[72], const float (*__restrict__ sv)[68],
    const float (*__restrict__ sp)[68], const float (*__restrict__ sq)[68],
    const float* __restrict__ vg,
    int tx, int ty, int i0, int j0, float& accC, float& accP)
{
    const int ev  = 2 * tx;          // even base col for v/p/q pairs
    const int eu  = ev + 2;          // even base col for u pairs
    const int lr0 = ty * 4 + 1;      // R of first output row
    const int ir0 = i0 + ty * 4;
    const int jA  = j0 + 2 * tx;
    const int jB  = jA + 1;

    float2 t;
    // ---- current row lr0 ----
    t = *(const float2*)&su[lr0][eu];   float u0 = t.y;               // u(jA-2)
    t = *(const float2*)&su[lr0][eu+2]; float u1 = t.x, u2 = t.y;     // u(jA-1), u(jA)
    t = *(const float2*)&su[lr0][eu+4]; float u3 = t.x, u4 = t.y;     // u(jB), u(jB+1)
    t = *(const float2*)&sv[lr0][ev];   float v0 = t.x, v1 = t.y;     // v(jA-1), v(jA)
    t = *(const float2*)&sv[lr0][ev+2]; float v2 = t.x, v3 = t.y;     // v(jB), v(jB+1)
    t = *(const float2*)&sp[lr0][ev];   float p0 = t.x, p1 = t.y;
    t = *(const float2*)&sp[lr0][ev+2]; float p2 = t.x, p3 = t.y;
    t = *(const float2*)&sq[lr0][ev];   float d0 = t.x - p0, d1 = t.y - p1;
    t = *(const float2*)&sq[lr0][ev+2]; float d2 = t.x - p2, d3 = t.y - p3;
    // ---- north row lr0-1 ----
    t = *(const float2*)&su[lr0-1][eu+2]; float uN1 = t.x, uN2 = t.y;
    t = *(const float2*)&su[lr0-1][eu+4]; float uN3 = t.x;
    t = *(const float2*)&sv[lr0-1][ev];   float w0 = t.x, w1 = t.y;
    t = *(const float2*)&sv[lr0-1][ev+2]; float w2 = t.x, w3 = t.y;
    t = *(const float2*)&sp[lr0-1][ev];   float pN1 = t.y;
    t = *(const float2*)&sp[lr0-1][ev+2]; float pN2 = t.x;
    t = *(const float2*)&sq[lr0-1][ev];   float dN1 = t.y - pN1;
    t = *(const float2*)&sq[lr0-1][ev+2]; float dN2 = t.x - pN2;
    // ---- vNN (row ir0-2): warp 0 reads global (row not in smem), others smem ----
    float vnnA, vnnB;
    if (ty == 0) {
        int gy = max(0, i0 - 2);                  // clamped value feeds guarded-out path only
        vnnA = vg[gy * S + jA];
        vnnB = vg[gy * S + min(jB, 511)];
    } else {
        t = *(const float2*)&sv[lr0-2][ev];   vnnA = t.y;
        t = *(const float2*)&sv[lr0-2][ev+2]; vnnB = t.x;
    }

    // ---- prologue fluxes (between rows ir0-1 and ir0) ----
    float prodNm = (0.5f*(w0+w1)) * (0.5f*(uN1+u1));
    float prodNA = (0.5f*(w1+w2)) * (0.5f*(uN2+u2));
    float prodNB = (0.5f*(w2+w3)) * (0.5f*(uN3+u3));
    float fnm = prodNm - (u1 - uN1);
    float fnA = prodNA - (u2 - uN2);
    float fnB = prodNB - (u3 - uN3);
    float gpa = 0.5f*(vnnA + w1); float gpA = gpa*gpa - (w1 - vnnA);
    float gpb = 0.5f*(vnnB + w2); float gpB = gpb*gpb - (w2 - vnnB);
    float geNm = prodNm - (w1 - w0);
    float geNA = prodNA - (w2 - w1);
    float geNB = prodNB - (w3 - w2);
    float ga2 = 0.5f*(w1 + v1); float gnA = ga2*ga2 - (v1 - w1);
    float gb2 = 0.5f*(w2 + v2); float gnB = gb2*gb2 - (v2 - w2);
    float dvNA = (-(geNA - geNm) - (gnA - gpA) - (p1 - pN1)) * 100.0f;
    float dvNB = (-(geNB - geNA) - (gnB - gpB) - (p2 - pN2)) * 100.0f;
    float vnA = w1 + dvNA * 0.001f;
    float vnB = w2 + dvNB * 0.001f;
    if (!INT) { if (ir0 - 1 < 1) { vnA = w1; vnB = w2; } }
    float vNA = w1, vNB = w2;

    #pragma unroll
    for (int k = 0; k < 4; k++) {
        const int lr = lr0 + k;
        const int i  = ir0 + k;
        // ---- south-row loads ----
        t = *(const float2*)&su[lr+1][eu];   float uS0 = t.y;
        t = *(const float2*)&su[lr+1][eu+2]; float uS1 = t.x, uS2 = t.y;
        t = *(const float2*)&su[lr+1][eu+4]; float uS3 = t.x, uS4 = t.y;
        t = *(const float2*)&sv[lr+1][ev];   float vS0 = t.x, vS1 = t.y;
        t = *(const float2*)&sv[lr+1][ev+2]; float vS2 = t.x, vS3 = t.y;
        t = *(const float2*)&sp[lr+1][ev];   float pS0 = t.x, pS1 = t.y;
        t = *(const float2*)&sp[lr+1][ev+2]; float pS2 = t.x, pS3 = t.y;
        t = *(const float2*)&sq[lr+1][ev];   float dS0 = t.x - pS0, dS1 = t.y - pS1;
        t = *(const float2*)&sq[lr+1][ev+2]; float dS2 = t.x - pS2, dS3 = t.y - pS3;

        // horizontal u fluxes
        float ha = 0.5f*(u0+u1); float feA = ha*ha - (u1-u0);
        float hb = 0.5f*(u1+u2); float feB = hb*hb - (u2-u1);
        float hc = 0.5f*(u2+u3); float feC = hc*hc - (u3-u2);
        float hd = 0.5f*(u3+u4); float feD = hd*hd - (u4-u3);
        // shared cross products at cols jA-1, jA, jB
        float prodm = (0.5f*(v0+v1)) * (0.5f*(u1+uS1));
        float prodA = (0.5f*(v1+v2)) * (0.5f*(u2+uS2));
        float prodB = (0.5f*(v2+v3)) * (0.5f*(u3+uS3));
        float fn_m = prodm - (uS1-u1);
        float fn_A = prodA - (uS2-u2);
        float fn_B = prodB - (uS3-u3);
        float dum = (-(feB-feA) - (fn_m-fnm) - (p1-p0)) * 100.0f;
        float duA = (-(feC-feB) - (fn_A-fnA) - (p2-p1)) * 100.0f;
        float duB = (-(feD-feC) - (fn_B-fnB) - (p3-p2)) * 100.0f;
        float unm = u1 + dum * 0.001f;
        float unA = u2 + duA * 0.001f;
        float unB = u3 + duB * 0.001f;
        float gem = prodm - (v1-v0);
        float geA = prodA - (v2-v1);
        float geB = prodB - (v3-v2);
        float g2a = 0.5f*(v1+vS1); float gn_A = g2a*g2a - (vS1-v1);
        float g2b = 0.5f*(v2+vS2); float gn_B = g2b*g2b - (vS2-v2);
        float dvA = (-(geA-gem) - (gn_A-gnA) - (pS1-p1)) * 100.0f;
        float dvB = (-(geB-geA) - (gn_B-gnB) - (pS2-p2)) * 100.0f;
        float vn_A = v1 + dvA * 0.001f;
        float vn_B = v2 + dvB * 0.001f;
        if (!INT) {
            const bool rowbad = (i > 510);
            if (jA - 1 < 1 || rowbad) unm = u1;
            if (jA > 509    || rowbad) unA = u2;
            if (jB > 509    || rowbad) unB = u3;
            if (i > 509) { vn_A = v1; vn_B = v2; }
        }
        float contA = (u2-u1 + v1-vNA) * 100.0f;
        float contB = (u3-u2 + v2-vNB) * 100.0f;
        float bcvA = ((unA-unm) + (vn_A-vnA)) * 100000.0f;
        float bcvB = ((unB-unA) + (vn_B-vnB)) * 100000.0f;
        float lapA = 4.0f*d1 - d0 - d2 - dS1 - dN1;
        float lapB = 4.0f*d2 - d1 - d3 - dS2 - dN2;
        float poisA = fmaf(lapA, 10000.0f, bcvA);
        float poisB = fmaf(lapB, 10000.0f, bcvB);
        if (INT || (i <= 510 && jA <= 510)) { accC += fabsf(contA); accP += fabsf(poisA); }
        if (INT || (i <= 510 && jB <= 510)) { accC += fabsf(contB); accP += fabsf(poisB); }

        // ---- roll ----
        fnm = fn_m; fnA = fn_A; fnB = fn_B;
        gnA = gn_A; gnB = gn_B; vnA = vn_A; vnB = vn_B;
        vNA = v1; vNB = v2; dN1 = d1; dN2 = d2;
        u0=uS0; u1=uS1; u2=uS2; u3=uS3; u4=uS4;
        v0=vS0; v1=vS1; v2=vS2; v3=vS3;
        p0=pS0; p1=pS1; p2=pS2; p3=pS3;
        d0=dS0; d1=dS1; d2=dS2; d3=dS3;
    }
}

__global__ __launch_bounds__(256, 6) void pil_kernel(const float* __restrict__ gen,
                                                     const float* __restrict__ pn,
                                                     float* __restrict__ out) {
    // tight halo tiles (34 rows = gy in [i0-1, i0+32])
    __shared__ __align__(16) float su_s[34][72];   // gx = bx*64-4+c
    __shared__ __align__(16) float sv_s[34][68];   // gx = bx*64+c
    __shared__ __align__(16) float sp_s[34][68];
    __shared__ __align__(16) float sq_s[34][68];
    __shared__ float redC[8], redP[8];
    __shared__ double dred[8];
    __shared__ unsigned int s_ticket;

    const int bx = blockIdx.x, by = blockIdx.y, b = blockIdx.z;
    const int i0 = 1 + by * 32;
    const int j0 = 1 + bx * 64;
    const int tid = threadIdx.x;
    const int tx = tid & 31, ty = tid >> 5;   // ty = warp id, 0..7

    const float* u = gen + (size_t)b * 3 * S2;
    const float* v = u + S2;
    const float* p = v + S2;
    const float* q = pn + (size_t)b * S2;

    // ---- slot decode: seg s in [0,69): u:0-17(18), v:18-34(17), p:35-51(17), q:52-68(17) ----
    auto decode = [&](int s, const float*& src, float*& dstc, int& strd,
                      bool& bad, const float*& fs) {
        if (s < 18) {
            int c = s;
            src = u + bx * 64 - 4 + c * 4; dstc = &su_s[0][0] + c * 4; strd = 72;
            bad = (bx == 0 && c == 0) || (bx == 7 && c == 17);
            fs = u + ((bx == 0) ? 0 : (S - 1));
        } else if (s < 35) {
            int c = s - 18;
            src = v + bx * 64 + c * 4; dstc = &sv_s[0][0] + c * 4; strd = 68;
            bad = (bx == 7 && c == 16); fs = v + (S - 1);
        } else if (s < 52) {
            int c = s - 35;
            src = p + bx * 64 + c * 4; dstc = &sp_s[0][0] + c * 4; strd = 68;
            bad = (bx == 7 && c == 16); fs = p + (S - 1);
        } else {
            int c = s - 52;
            src = q + bx * 64 + c * 4; dstc = &sq_s[0][0] + c * 4; strd = 68;
            bad = (bx == 7 && c == 16); fs = q + (S - 1);
        }
    };
    const float *src0, *fs0, *src1, *fs1, *src2, *fs2;
    float *dst0, *dst1, *dst2;
    int st0, st1, st2; bool bad0, bad1, bad2;
    decode(tx,      src0, dst0, st0, bad0, fs0);
    decode(tx + 32, src1, dst1, st1, bad1, fs1);
    const bool haveS2 = (tx < 5);
    decode(haveS2 ? tx + 64 : 0, src2, dst2, st2, bad2, fs2);

    // ---- load (dedup): warp ty fills rows ty*4..ty*4+3; warps 0,1 take rows 32,33 ----
    #pragma unroll
    for (int rl = 0; rl < 5; rl++) {
        int R = (rl < 4) ? (ty * 4 + rl) : (32 + ty);
        if (rl == 4 && ty >= 2) break;
        int gy = min(S - 1, i0 - 1 + R);          // min index is 0 exactly (by=0)
        const int ro = gy * S;
        if (!bad0) __pipeline_memcpy_async(dst0 + R * st0, src0 + ro, 16);
        else { float vv = fs0[ro]; float* d = dst0 + R * st0; d[0]=vv; d[1]=vv; d[2]=vv; d[3]=vv; }
        if (!bad1) __pipeline_memcpy_async(dst1 + R * st1, src1 + ro, 16);
        else { float vv = fs1[ro]; float* d = dst1 + R * st1; d[0]=vv; d[1]=vv; d[2]=vv; d[3]=vv; }
        if (haveS2) {
            if (!bad2) __pipeline_memcpy_async(dst2 + R * st2, src2 + ro, 16);
            else { float vv = fs2[ro]; float* d = dst2 + R * st2; d[0]=vv; d[1]=vv; d[2]=vv; d[3]=vv; }
        }
    }
    __pipeline_commit();
    __pipeline_wait_prior(0);
    __syncthreads();

    float accC = 0.0f, accP = 0.0f;
    const bool interior = (bx >= 1) && (bx <= 6) && (by >= 1) && (by <= 14);
    if (interior) {
        tile_compute<true >(su_s, sv_s, sp_s, sq_s, v, tx, ty, i0, j0, accC, accP);
    } else {
        tile_compute<false>(su_s, sv_s, sp_s, sq_s, v, tx, ty, i0, j0, accC, accP);

        // ---- boundary-condition edge sums (edge blocks, from smem) ----
        float es = 0.0f; int eidx = -1;
        if (tid < 64) {                       // top/bottom: 64 cols (warps 0,1)
            int jj = j0 + tid;
            int cu = tid + 5, cv = tid + 1;
            if (by == 0) {                    // gy 0 -> R=0, gy 1 -> R=1
                eidx = 0;
                if (jj <= 509) es += su_s[0][cu] + su_s[1][cu];
                if (jj <= 510) es += sv_s[0][cv] + sp_s[0][cv];
            } else if (by == 15) {            // gy 510 -> R=30, gy 511 -> R=31
                eidx = 1;
                if (jj <= 509) es += 2.0f - (su_s[30][cu] + su_s[31][cu]);
                if (jj <= 510) es += sv_s[31][cv] + sp_s[31][cv];
            }
        } else if (tid < 96) {                // left/right: 32 rows (warp 2)
            int lane = tid - 64;              // 0..31
            int ii = i0 + lane, lrr = lane + 1;
            if (bx == 0) {                    // gx0: u col 4, v/p col 0; gx1: v col 1
                eidx = 2;
                if (ii <= 509) es += sv_s[lrr][0] + sv_s[lrr][1];
                if (ii <= 510) es += su_s[lrr][4] + sp_s[lrr][0];
            } else if (bx == 7) {             // gx510: v col 62; gx511: u col 67, v/p col 63
                eidx = 3;
                if (ii <= 509) es += sv_s[lrr][63] + sv_s[lrr][62];
                if (ii <= 510) es += su_s[lrr][67] + sp_s[lrr][63];
            }
        }
        if (eidx >= 0) {                      // warp-uniform per warp
            #pragma unroll
            for (int off = 16; off > 0; off >>= 1)
                es += __shfl_down_sync(0xFFFFFFFFu, es, off);
            if ((tid & 31) == 0)
                atomicAdd(&g_bc4[b * 4 + eidx], (double)es);
        }
    }

    // ---- block reduction of residual sums ----
    #pragma unroll
    for (int off = 16; off > 0; off >>= 1) {
        accC += __shfl_down_sync(0xFFFFFFFFu, accC, off);
        accP += __shfl_down_sync(0xFFFFFFFFu, accP, off);
    }
    if (tx == 0) { redC[ty] = accC; redP[ty] = accP; }
    __syncthreads();
    if (ty == 0) {
        float rc = (tx < 8) ? redC[tx] : 0.0f;
        float rp = (tx < 8) ? redP[tx] : 0.0f;
        #pragma unroll
        for (int off = 4; off > 0; off >>= 1) {
            rc += __shfl_down_sync(0xFFFFFFFFu, rc, off);
            rp += __shfl_down_sync(0xFFFFFFFFu, rp, off);
        }
        if (tx == 0) {
            atomicAdd(&g_acc[0], (double)rc);
            atomicAdd(&g_acc[1], (double)rp);
        }
    }

    // ---- last-block finalize ----
    __threadfence();
    if (tid == 0) s_ticket = atomicAdd(&g_count, 1u);
    __syncthreads();
    if (s_ticket == NBLK_TOTAL - 1u) {
        double mybc = 0.0;
        if (tid < NBATCH * 4)
            mybc = fabs(atomicAdd(&g_bc4[tid], 0.0));
        #pragma unroll
        for (int off = 16; off > 0; off >>= 1)
            mybc += __shfl_down_sync(0xFFFFFFFFu, mybc, off);
        if (tx == 0) dred[ty] = mybc;
        __syncthreads();
        if (tid == 0) {
            double bc = 0.0;
            #pragma unroll
            for (int kk = 0; kk < 8; kk++) bc += dred[kk];
            double C = atomicAdd(&g_acc[0], 0.0);
            double P = atomicAdd(&g_acc[1], 0.0);
            double denom = 32.0 * 510.0 * 510.0;
            out[0] = (float)(0.4 * (C / denom) + 0.2 * bc + (1.0 - 0.4 - 0.2) * (P / denom));
            g_acc[0] = 0.0; g_acc[1] = 0.0;
        }
        if (tid < NBATCH * 4) g_bc4[tid] = 0.0;
        __threadfence();
        __syncthreads();
        if (tid == 0) g_count = 0u;
    }
}

extern "C" void kernel_launch(void* const* d_in, const int* in_sizes, int n_in,
                              void* d_out, int out_size) {
    const float* gen = (const float*)d_in[0];
    const float* pn  = (const float*)d_in[1];
    float* out = (float*)d_out;
    dim3 grid(8, 16, NBATCH);   // 8 x 16 x 32 = 4096 blocks
    pil_kernel<<<grid, 256>>>(gen, pn, out);
}